// round 12
// baseline (speedup 1.0000x reference)
#include <cuda_runtime.h>
#include <cuda_fp16.h>
#include <cstdint>

// Problem constants (fixed by the dataset)
#define NMAX 100000
#define EMAX 3200000
#define F0 512
#define F1 256
#define F2 40

// ---------------- scratch (static __device__, no allocation) ----------------
__device__ int    g_is64;            // 1 if edge_index is int64, 0 if int32
__device__ int    g_deg[NMAX];
__device__ float  g_dinv[NMAX];
__device__ int    g_rowstart[NMAX + 1];
__device__ int    g_cursor[NMAX];
__device__ int    g_blksum[128];
__device__ int    g_blkoff[128];
__device__ int    g_csr_src[EMAX];
__device__ __align__(16) __half g_w1h[(size_t)F0 * F1];   // W1 in fp16
__device__ __align__(16) __half g_h1[(size_t)NMAX * F1];  // (x@W1)*dinv[row], fp16
__device__ __align__(16) __half g_a1[(size_t)NMAX * F1];  // relu(agg1 + b1), fp16
__device__ __align__(16) __half g_h2[(size_t)NMAX * F2];  // (a1@W2)*dinv[row], fp16

__device__ __forceinline__ uint32_t smem_u32(const void* p) {
    return (uint32_t)__cvta_generic_to_shared(p);
}
__device__ __forceinline__ void cp16(void* dst, const void* src) {
    asm volatile("cp.async.cg.shared.global [%0], [%1], 16;"
        :: "r"(smem_u32(dst)), "l"(src));
}
__device__ __forceinline__ void cp16z(void* dst, const void* src, bool valid) {
    int sz = valid ? 16 : 0;
    asm volatile("cp.async.cg.shared.global [%0], [%1], 16, %2;"
        :: "r"(smem_u32(dst)), "l"(src), "r"(sz));
}

// ---------------- 0. detect edge_index dtype ----------------
__global__ void k_detect(const int* __restrict__ w) {
    __shared__ int s_nonzero;
    if (threadIdx.x == 0) s_nonzero = 0;
    __syncthreads();
    int nz = 0;
    for (int i = threadIdx.x; i < 2048; i += blockDim.x)
        nz |= (w[2 * i + 1] != 0);
    if (nz) atomicOr(&s_nonzero, 1);
    __syncthreads();
    if (threadIdx.x == 0) g_is64 = s_nonzero ? 0 : 1;
}

// ---------------- 0b. convert W1 to fp16 + zero degree (fused) ----------------
__global__ void k_prep(const float* __restrict__ W1, int n) {
    int i = blockIdx.x * blockDim.x + threadIdx.x;
    if (i < F0 * F1 / 2) {
        float2 v = *(const float2*)&W1[2 * i];
        *(__half2*)&g_w1h[2 * i] = __floats2half2_rn(v.x, v.y);
    }
    if (i < n) g_deg[i] = 0;
}

// ---------------- 2. count in-degree (4 edges/thread) ----------------
__global__ void k_count(const void* __restrict__ ei, int E) {
    int e = (blockIdx.x * blockDim.x + threadIdx.x) * 4;
    if (e >= E) return;
    if (((E & 3) == 0) && (e + 3 < E)) {
        int d0, d1, d2, d3;
        if (g_is64) {
            const int4* p = (const int4*)((const long long*)ei + (size_t)E + e);
            int4 a = p[0], b = p[1];
            d0 = a.x; d1 = a.z; d2 = b.x; d3 = b.z;
        } else {
            int4 a = *(const int4*)((const int*)ei + (size_t)E + e);
            d0 = a.x; d1 = a.y; d2 = a.z; d3 = a.w;
        }
        atomicAdd(&g_deg[d0], 1);
        atomicAdd(&g_deg[d1], 1);
        atomicAdd(&g_deg[d2], 1);
        atomicAdd(&g_deg[d3], 1);
    } else {
        for (int q = e; q < E && q < e + 4; q++) {
            int d = g_is64 ? (int)((const long long*)ei)[(size_t)E + q]
                           : ((const int*)ei)[(size_t)E + q];
            atomicAdd(&g_deg[d], 1);
        }
    }
}

// ---------------- 3a. per-block exclusive scan of deg ----------------
__global__ void k_scan_blk(int n) {
    __shared__ int s_wsum[32];
    int tid = threadIdx.x, lane = tid & 31, wid = tid >> 5;
    int i = blockIdx.x * 1024 + tid;
    int deg = (i < n) ? g_deg[i] : 0;
    int x = deg;
    #pragma unroll
    for (int o = 1; o < 32; o <<= 1) {
        int t = __shfl_up_sync(0xffffffffu, x, o);
        if (lane >= o) x += t;
    }
    if (lane == 31) s_wsum[wid] = x;
    __syncthreads();
    if (wid == 0) {
        int w = s_wsum[lane];
        #pragma unroll
        for (int o = 1; o < 32; o <<= 1) {
            int t = __shfl_up_sync(0xffffffffu, w, o);
            if (lane >= o) w += t;
        }
        s_wsum[lane] = w;
    }
    __syncthreads();
    int base = (wid ? s_wsum[wid - 1] : 0);
    if (i < n) g_rowstart[i] = base + x - deg;
    if (tid == 1023) g_blksum[blockIdx.x] = base + x;
}

// ---------------- 3b. scan of block sums (single block) ----------------
__global__ void k_scan_top(int nblk) {
    __shared__ int s_wsum[4];
    int tid = threadIdx.x, lane = tid & 31, wid = tid >> 5;
    int v = (tid < nblk) ? g_blksum[tid] : 0;
    int x = v;
    #pragma unroll
    for (int o = 1; o < 32; o <<= 1) {
        int t = __shfl_up_sync(0xffffffffu, x, o);
        if (lane >= o) x += t;
    }
    if (lane == 31) s_wsum[wid] = x;
    __syncthreads();
    if (tid < 4) {
        int w = s_wsum[tid];
        #pragma unroll
        for (int o = 1; o < 4; o <<= 1) {
            int t = __shfl_up_sync(0xfu, w, o);
            if ((tid & 3) >= o) w += t;
        }
        s_wsum[tid] = w;
    }
    __syncthreads();
    int base = (wid ? s_wsum[wid - 1] : 0);
    if (tid < nblk) g_blkoff[tid] = base + x - v;
}

// ---------------- 3c. add offsets, derive cursor + dinv ----------------
__global__ void k_scan_add(int n, int E) {
    int i = blockIdx.x * blockDim.x + threadIdx.x;
    if (i < n) {
        int rs = g_rowstart[i] + g_blkoff[blockIdx.x >> 2];
        g_rowstart[i] = rs;
        g_cursor[i]   = rs;
        g_dinv[i]     = rsqrtf((float)(g_deg[i] + 1));
    }
    if (i == 0) g_rowstart[n] = E;
}

// ---------------- 4. fill CSR (4 edges/thread) ----------------
__global__ void k_fill(const void* __restrict__ ei, int E) {
    int e = (blockIdx.x * blockDim.x + threadIdx.x) * 4;
    if (e >= E) return;
    if (((E & 3) == 0) && (e + 3 < E)) {
        int s0, s1, s2, s3, d0, d1, d2, d3;
        if (g_is64) {
            const int4* ps = (const int4*)((const long long*)ei + e);
            int4 a = ps[0], b = ps[1];
            s0 = a.x; s1 = a.z; s2 = b.x; s3 = b.z;
            const int4* pd = (const int4*)((const long long*)ei + (size_t)E + e);
            int4 c = pd[0], d = pd[1];
            d0 = c.x; d1 = c.z; d2 = d.x; d3 = d.z;
        } else {
            int4 a = *(const int4*)((const int*)ei + e);
            s0 = a.x; s1 = a.y; s2 = a.z; s3 = a.w;
            int4 b = *(const int4*)((const int*)ei + (size_t)E + e);
            d0 = b.x; d1 = b.y; d2 = b.z; d3 = b.w;
        }
        g_csr_src[atomicAdd(&g_cursor[d0], 1)] = s0;
        g_csr_src[atomicAdd(&g_cursor[d1], 1)] = s1;
        g_csr_src[atomicAdd(&g_cursor[d2], 1)] = s2;
        g_csr_src[atomicAdd(&g_cursor[d3], 1)] = s3;
    } else {
        for (int q = e; q < E && q < e + 4; q++) {
            int s, d;
            if (g_is64) {
                s = (int)((const long long*)ei)[q];
                d = (int)((const long long*)ei)[(size_t)E + q];
            } else {
                s = ((const int*)ei)[q];
                d = ((const int*)ei)[(size_t)E + q];
            }
            g_csr_src[atomicAdd(&g_cursor[d], 1)] = s;
        }
    }
}

// ---------------- 5. GEMM1 (tensor cores, cp.async pipelined) ----------------
// BM=64, BN=256 (full N -> x read exactly once), BK=64, 8 warps, double-buffered.
// raw stride = 68 floats = 272 B = 17*16 -> every cp.async dst is 16B-aligned.
#define G1_SB_HALFS 16384
#define G1_SA_HALFS 4096
#define G1_RAW_STRIDE 68
#define G1_RAW_FLTS (64 * G1_RAW_STRIDE)
#define G1_SMEM (2 * (G1_SB_HALFS * 2 + G1_SA_HALFS * 2 + G1_RAW_FLTS * 4))

__device__ __forceinline__ void g1_stage(const float* __restrict__ A, int M, int row0,
                                         int kt, __half* sB, float* raw, int tid) {
    int k0 = kt * 64;
    #pragma unroll
    for (int i = 0; i < 8; i++) {
        int cid = tid + i * 256;
        int r = cid >> 5, ch = cid & 31;
        cp16(&sB[r * 256 + ((ch ^ (r & 7)) * 8)],
             &g_w1h[(size_t)(k0 + r) * F1 + ch * 8]);
    }
    #pragma unroll
    for (int i = 0; i < 4; i++) {
        int cid = tid + i * 256;
        int r = cid >> 4, c = cid & 15;
        cp16z(&raw[r * G1_RAW_STRIDE + c * 4],
              &A[(size_t)(row0 + r) * F0 + k0 + c * 4], (row0 + r) < M);
    }
    asm volatile("cp.async.commit_group;");
}

__device__ __forceinline__ void g1_convert(__half* sA, const float* raw, int tid) {
    #pragma unroll
    for (int i = 0; i < 2; i++) {
        int cid = tid + i * 256;
        int r = cid >> 3, ch = cid & 7;
        const float* rp = &raw[r * G1_RAW_STRIDE + ch * 8];
        __half2 h0 = __floats2half2_rn(rp[0], rp[1]);
        __half2 h1 = __floats2half2_rn(rp[2], rp[3]);
        __half2 h2 = __floats2half2_rn(rp[4], rp[5]);
        __half2 h3 = __floats2half2_rn(rp[6], rp[7]);
        uint4 pk;
        pk.x = *(unsigned*)&h0; pk.y = *(unsigned*)&h1;
        pk.z = *(unsigned*)&h2; pk.w = *(unsigned*)&h3;
        *(uint4*)&sA[r * 64 + ((ch ^ (r & 7)) * 8)] = pk;
    }
}

__global__ __launch_bounds__(256, 2) void k_gemm1_tc(
    const float* __restrict__ A, int M
) {
    extern __shared__ __align__(16) char dyn[];
    __half* sBb  = (__half*)dyn;                                       // 2 x 32KB
    __half* sAb  = (__half*)(dyn + 2 * G1_SB_HALFS * 2);               // 2 x 8KB
    float*  rawb = (float*)(dyn + 2 * G1_SB_HALFS * 2 + 2 * G1_SA_HALFS * 2);
    int tid = threadIdx.x;
    int lane = tid & 31, wid = tid >> 5;
    int warp_m = wid & 1;
    int warp_n = wid >> 1;
    int row0 = blockIdx.x * 64;

    float acc[2][8][4];
    #pragma unroll
    for (int mt = 0; mt < 2; mt++)
        #pragma unroll
        for (int nt = 0; nt < 8; nt++)
            #pragma unroll
            for (int q = 0; q < 4; q++) acc[mt][nt][q] = 0.f;

    // prologue: stage tile 0, convert
    g1_stage(A, M, row0, 0, sBb, rawb, tid);
    asm volatile("cp.async.wait_group 0;");
    __syncthreads();
    g1_convert(sAb, rawb, tid);

    for (int kt = 0; kt < 8; kt++) {
        int cur = kt & 1, nxt = cur ^ 1;
        if (kt < 7)
            g1_stage(A, M, row0, kt + 1, sBb + nxt * G1_SB_HALFS,
                     rawb + nxt * G1_RAW_FLTS, tid);
        __syncthreads();   // convert(cur) visible to all warps

        const __half* sA = sAb + cur * G1_SA_HALFS;
        const __half* sB = sBb + cur * G1_SB_HALFS;
        #pragma unroll
        for (int ks = 0; ks < 4; ks++) {
            int kb = ks * 16;
            int j = lane >> 3;
            int jr = lane & 7;
            uint32_t afr[2][4];
            #pragma unroll
            for (int mt = 0; mt < 2; mt++) {
                int r = warp_m * 32 + mt * 16 + jr + ((j & 1) ? 8 : 0);
                int kk = kb + ((j & 2) ? 8 : 0);
                int ch = (kk >> 3) ^ (r & 7);
                uint32_t addr = smem_u32(&sA[r * 64 + ch * 8]);
                asm volatile("ldmatrix.sync.aligned.m8n8.x4.shared.b16 {%0,%1,%2,%3}, [%4];"
                    : "=r"(afr[mt][0]), "=r"(afr[mt][1]), "=r"(afr[mt][2]), "=r"(afr[mt][3])
                    : "r"(addr));
            }
            uint32_t bfr[8][2];
            #pragma unroll
            for (int nq = 0; nq < 4; nq++) {
                int r = kb + jr + ((j & 1) ? 8 : 0);
                int nn = warp_n * 64 + nq * 16 + ((j & 2) ? 8 : 0);
                int ch = (nn >> 3) ^ (r & 7);
                uint32_t addr = smem_u32(&sB[r * 256 + ch * 8]);
                asm volatile("ldmatrix.sync.aligned.m8n8.x4.trans.shared.b16 {%0,%1,%2,%3}, [%4];"
                    : "=r"(bfr[nq * 2][0]), "=r"(bfr[nq * 2][1]),
                      "=r"(bfr[nq * 2 + 1][0]), "=r"(bfr[nq * 2 + 1][1])
                    : "r"(addr));
            }
            #pragma unroll
            for (int mt = 0; mt < 2; mt++)
                #pragma unroll
                for (int nt = 0; nt < 8; nt++) {
                    asm volatile(
                        "mma.sync.aligned.m16n8k16.row.col.f32.f16.f16.f32 "
                        "{%0,%1,%2,%3}, {%4,%5,%6,%7}, {%8,%9}, {%0,%1,%2,%3};"
                        : "+f"(acc[mt][nt][0]), "+f"(acc[mt][nt][1]),
                          "+f"(acc[mt][nt][2]), "+f"(acc[mt][nt][3])
                        : "r"(afr[mt][0]), "r"(afr[mt][1]), "r"(afr[mt][2]), "r"(afr[mt][3]),
                          "r"(bfr[nt][0]), "r"(bfr[nt][1]));
                }
        }

        if (kt < 7) {
            asm volatile("cp.async.wait_group 0;");
            __syncthreads();   // staged data of tile kt+1 visible
            g1_convert(sAb + nxt * G1_SA_HALFS, rawb + nxt * G1_RAW_FLTS, tid);
        }
    }

    // epilogue: scale by dinv[row], pack fp16, store
    int quad = lane >> 2, tig = lane & 3;
    #pragma unroll
    for (int mt = 0; mt < 2; mt++) {
        int r0 = row0 + warp_m * 32 + mt * 16 + quad;
        int r1 = r0 + 8;
        float dv0 = (r0 < M) ? g_dinv[r0] : 0.f;
        float dv1 = (r1 < M) ? g_dinv[r1] : 0.f;
        #pragma unroll
        for (int nt = 0; nt < 8; nt++) {
            int c = warp_n * 64 + nt * 8 + tig * 2;
            if (r0 < M) {
                __half2 h = __floats2half2_rn(acc[mt][nt][0] * dv0, acc[mt][nt][1] * dv0);
                *(__half2*)&g_h1[(size_t)r0 * F1 + c] = h;
            }
            if (r1 < M) {
                __half2 h = __floats2half2_rn(acc[mt][nt][2] * dv1, acc[mt][nt][3] * dv1);
                *(__half2*)&g_h1[(size_t)r1 * F1 + c] = h;
            }
        }
    }
}

// ---------------- 6. agg1: one warp per dst node, fp16 gather / fp32 accum ----
__device__ __forceinline__ void acc_row(float* acc, uint4 v) {
    const __half2* h = (const __half2*)&v;
    #pragma unroll
    for (int q = 0; q < 4; q++) {
        float2 f = __half22float2(h[q]);
        acc[2 * q]     += f.x;
        acc[2 * q + 1] += f.y;
    }
}

__global__ void k_agg1(const float* __restrict__ b1, int n) {
    int w = (blockIdx.x * blockDim.x + threadIdx.x) >> 5;
    if (w >= n) return;
    int lane = threadIdx.x & 31;
    int beg = g_rowstart[w], end = g_rowstart[w + 1];
    const size_t laneoff = (size_t)lane * 8;
    float acc[8];
    {
        uint4 v = *(const uint4*)&g_h1[(size_t)w * F1 + laneoff];
        const __half2* h = (const __half2*)&v;
        #pragma unroll
        for (int q = 0; q < 4; q++) {
            float2 f = __half22float2(h[q]);
            acc[2 * q] = f.x;
            acc[2 * q + 1] = f.y;
        }
    }
    int p = beg;
    for (; p + 1 < end; p += 2) {
        int s0 = g_csr_src[p];
        int s1 = g_csr_src[p + 1];
        uint4 v0 = *(const uint4*)&g_h1[(size_t)s0 * F1 + laneoff];
        uint4 v1 = *(const uint4*)&g_h1[(size_t)s1 * F1 + laneoff];
        acc_row(acc, v0);
        acc_row(acc, v1);
    }
    if (p < end) {
        int s0 = g_csr_src[p];
        uint4 v0 = *(const uint4*)&g_h1[(size_t)s0 * F1 + laneoff];
        acc_row(acc, v0);
    }
    float dv = g_dinv[w];
    float4 bb0 = *(const float4*)&b1[laneoff];
    float4 bb1 = *(const float4*)&b1[laneoff + 4];
    __half2 o[4];
    o[0] = __floats2half2_rn(fmaxf(acc[0] * dv + bb0.x, 0.f), fmaxf(acc[1] * dv + bb0.y, 0.f));
    o[1] = __floats2half2_rn(fmaxf(acc[2] * dv + bb0.z, 0.f), fmaxf(acc[3] * dv + bb0.w, 0.f));
    o[2] = __floats2half2_rn(fmaxf(acc[4] * dv + bb1.x, 0.f), fmaxf(acc[5] * dv + bb1.y, 0.f));
    o[3] = __floats2half2_rn(fmaxf(acc[6] * dv + bb1.z, 0.f), fmaxf(acc[7] * dv + bb1.w, 0.f));
    uint4 pk;
    pk.x = *(unsigned*)&o[0]; pk.y = *(unsigned*)&o[1];
    pk.z = *(unsigned*)&o[2]; pk.w = *(unsigned*)&o[3];
    *(uint4*)&g_a1[(size_t)w * F1 + laneoff] = pk;
}

// ---------------- 7. GEMM2 (tensor cores): g_h2 = fp16((a1 @ W2) * dinv[row]) --
__global__ __launch_bounds__(256, 2) void k_gemm2_tc(const float* __restrict__ W2, int M) {
    __shared__ __align__(16) __half sA[128 * 64];
    __shared__ __align__(16) __half sW[64 * 40];
    int tid = threadIdx.x;
    int lane = tid & 31, wid = tid >> 5;
    int row0 = blockIdx.x * 128;

    float acc[5][4];
    #pragma unroll
    for (int nt = 0; nt < 5; nt++)
        #pragma unroll
        for (int q = 0; q < 4; q++) acc[nt][q] = 0.f;

    for (int k0 = 0; k0 < F1; k0 += 64) {
        #pragma unroll
        for (int i = 0; i < 4; i++) {
            int cid = tid + i * 256;
            int r = cid >> 3, ch = cid & 7;
            int gr = row0 + r;
            uint4 pk = make_uint4(0, 0, 0, 0);
            if (gr < M) pk = *(const uint4*)&g_a1[(size_t)gr * F1 + k0 + ch * 8];
            int sch = ch ^ (r & 7);
            *(uint4*)&sA[r * 64 + sch * 8] = pk;
        }
        #pragma unroll
        for (int i = 0; i < 10; i++) {
            int idx = tid + i * 256;
            int r = idx / 40, c = idx % 40;
            sW[r * 40 + c] = __float2half(W2[(size_t)(k0 + r) * F2 + c]);
        }
        __syncthreads();

        #pragma unroll
        for (int ks = 0; ks < 4; ks++) {
            int kb = ks * 16;
            int j = lane >> 3;
            int jr = lane & 7;
            uint32_t afr[4];
            {
                int r = wid * 16 + jr + ((j & 1) ? 8 : 0);
                int kk = kb + ((j & 2) ? 8 : 0);
                int ch = (kk >> 3) ^ (r & 7);
                uint32_t addr = smem_u32(&sA[r * 64 + ch * 8]);
                asm volatile("ldmatrix.sync.aligned.m8n8.x4.shared.b16 {%0,%1,%2,%3}, [%4];"
                    : "=r"(afr[0]), "=r"(afr[1]), "=r"(afr[2]), "=r"(afr[3])
                    : "r"(addr));
            }
            uint32_t bfr[5][2];
            #pragma unroll
            for (int nq = 0; nq < 2; nq++) {
                int r = kb + jr + ((j & 1) ? 8 : 0);
                int nn = nq * 16 + ((j & 2) ? 8 : 0);
                uint32_t addr = smem_u32(&sW[r * 40 + nn]);
                asm volatile("ldmatrix.sync.aligned.m8n8.x4.trans.shared.b16 {%0,%1,%2,%3}, [%4];"
                    : "=r"(bfr[nq * 2][0]), "=r"(bfr[nq * 2][1]),
                      "=r"(bfr[nq * 2 + 1][0]), "=r"(bfr[nq * 2 + 1][1])
                    : "r"(addr));
            }
            {
                int j2 = (lane >> 3) & 1;
                int r = kb + jr + (j2 ? 8 : 0);
                uint32_t addr = smem_u32(&sW[r * 40 + 32]);
                asm volatile("ldmatrix.sync.aligned.m8n8.x2.trans.shared.b16 {%0,%1}, [%2];"
                    : "=r"(bfr[4][0]), "=r"(bfr[4][1])
                    : "r"(addr));
            }
            #pragma unroll
            for (int nt = 0; nt < 5; nt++) {
                asm volatile(
                    "mma.sync.aligned.m16n8k16.row.col.f32.f16.f16.f32 "
                    "{%0,%1,%2,%3}, {%4,%5,%6,%7}, {%8,%9}, {%0,%1,%2,%3};"
                    : "+f"(acc[nt][0]), "+f"(acc[nt][1]), "+f"(acc[nt][2]), "+f"(acc[nt][3])
                    : "r"(afr[0]), "r"(afr[1]), "r"(afr[2]), "r"(afr[3]),
                      "r"(bfr[nt][0]), "r"(bfr[nt][1]));
            }
        }
        __syncthreads();
    }

    int quad = lane >> 2, tig = lane & 3;
    int r0 = row0 + wid * 16 + quad;
    int r1 = r0 + 8;
    float dv0 = (r0 < M) ? g_dinv[r0] : 0.f;
    float dv1 = (r1 < M) ? g_dinv[r1] : 0.f;
    #pragma unroll
    for (int nt = 0; nt < 5; nt++) {
        int c = nt * 8 + tig * 2;
        if (r0 < M) {
            __half2 h = __floats2half2_rn(acc[nt][0] * dv0, acc[nt][1] * dv0);
            *(__half2*)&g_h2[(size_t)r0 * F2 + c] = h;
        }
        if (r1 < M) {
            __half2 h = __floats2half2_rn(acc[nt][2] * dv1, acc[nt][3] * dv1);
            *(__half2*)&g_h2[(size_t)r1 * F2 + c] = h;
        }
    }
}

// ---------------- 8. agg2 + bias + log_softmax: one warp per node ----------------
__global__ void k_agg2(const float* __restrict__ b2, float* __restrict__ out, int n) {
    int w = (blockIdx.x * blockDim.x + threadIdx.x) >> 5;
    if (w >= n) return;
    int lane = threadIdx.x & 31;
    int beg = g_rowstart[w], end = g_rowstart[w + 1];
    const __half* selfr = &g_h2[(size_t)w * F2];
    float a0 = __half2float(selfr[lane]);
    float a1 = (lane < 8) ? __half2float(selfr[32 + lane]) : 0.f;
    for (int p = beg; p < end; p++) {
        int s = g_csr_src[p];
        const __half* r = &g_h2[(size_t)s * F2];
        a0 += __half2float(r[lane]);
        if (lane < 8) a1 += __half2float(r[32 + lane]);
    }
    float dv = g_dinv[w];
    const float NEGINF = __int_as_float(0xff800000);
    float v0 = a0 * dv + b2[lane];
    float v1 = (lane < 8) ? (a1 * dv + b2[32 + lane]) : NEGINF;
    float m = fmaxf(v0, v1);
    #pragma unroll
    for (int o = 16; o; o >>= 1) m = fmaxf(m, __shfl_xor_sync(0xffffffffu, m, o));
    float s1 = __expf(v0 - m) + ((lane < 8) ? __expf(v1 - m) : 0.f);
    #pragma unroll
    for (int o = 16; o; o >>= 1) s1 += __shfl_xor_sync(0xffffffffu, s1, o);
    float ls = m + __logf(s1);
    out[(size_t)w * F2 + lane] = v0 - ls;
    if (lane < 8) out[(size_t)w * F2 + 32 + lane] = v1 - ls;
}

// ---------------- launch ----------------
extern "C" void kernel_launch(void* const* d_in, const int* in_sizes, int n_in,
                              void* d_out, int out_size) {
    const float* x  = (const float*)d_in[0];
    const void*  ei = (const void*)d_in[1];
    const float* W1 = (const float*)d_in[2];
    const float* b1 = (const float*)d_in[3];
    const float* W2 = (const float*)d_in[4];
    const float* b2 = (const float*)d_in[5];
    float* out = (float*)d_out;

    int n = in_sizes[0] / F0;     // 100000
    int E = in_sizes[1] / 2;      // 3200000
    int nblk = (n + 1023) >> 10;
    int prep_items = (F0 * F1 / 2 > n) ? F0 * F1 / 2 : n;

    cudaFuncSetAttribute(k_gemm1_tc, cudaFuncAttributeMaxDynamicSharedMemorySize, G1_SMEM);

    k_detect<<<1, 256>>>((const int*)ei);
    k_prep<<<(prep_items + 255) / 256, 256>>>(W1, n);
    k_count<<<(E / 4 + 255) / 256, 256>>>(ei, E);
    k_scan_blk<<<nblk, 1024>>>(n);
    k_scan_top<<<1, 128>>>(nblk);
    k_scan_add<<<(n + 255) / 256, 256>>>(n, E);
    k_fill<<<(E / 4 + 255) / 256, 256>>>(ei, E);

    k_gemm1_tc<<<(n + 63) / 64, 256, G1_SMEM>>>(x, n);

    k_agg1<<<(n * 32 + 255) / 256, 256>>>(b1, n);

    k_gemm2_tc<<<(n + 127) / 128, 256>>>(W2, n);

    k_agg2<<<(n * 32 + 255) / 256, 256>>>(b2, out, n);
}

// round 13
// speedup vs baseline: 1.0679x; 1.0679x over previous
#include <cuda_runtime.h>
#include <cuda_fp16.h>
#include <cstdint>

// Problem constants (fixed by the dataset)
#define NMAX 100000
#define EMAX 3200000
#define F0 512
#define F1 256
#define F2 40

// ---------------- scratch (static __device__, no allocation) ----------------
__device__ int    g_is64;            // 1 if edge_index is int64, 0 if int32
__device__ int    g_deg[NMAX];
__device__ float  g_dinv[NMAX];
__device__ int    g_rowstart[NMAX + 1];
__device__ int    g_cursor[NMAX];
__device__ int    g_blksum[128];
__device__ int    g_blkoff[128];
__device__ int    g_csr_src[EMAX];
__device__ __align__(16) __half g_w1h[(size_t)F0 * F1];   // W1 in fp16
__device__ __align__(16) __half g_h1[(size_t)NMAX * F1];  // (x@W1)*dinv[row], fp16
__device__ __align__(16) __half g_a1[(size_t)NMAX * F1];  // relu(agg1 + b1), fp16
__device__ __align__(16) __half g_h2[(size_t)NMAX * F2];  // (a1@W2)*dinv[row], fp16

__device__ __forceinline__ uint32_t smem_u32(const void* p) {
    return (uint32_t)__cvta_generic_to_shared(p);
}
__device__ __forceinline__ void cp16(void* dst, const void* src) {
    asm volatile("cp.async.cg.shared.global [%0], [%1], 16;"
        :: "r"(smem_u32(dst)), "l"(src));
}
__device__ __forceinline__ void cp16z(void* dst, const void* src, bool valid) {
    int sz = valid ? 16 : 0;
    asm volatile("cp.async.cg.shared.global [%0], [%1], 16, %2;"
        :: "r"(smem_u32(dst)), "l"(src), "r"(sz));
}

// ---------------- 0. detect edge_index dtype ----------------
__global__ void k_detect(const int* __restrict__ w) {
    __shared__ int s_nonzero;
    if (threadIdx.x == 0) s_nonzero = 0;
    __syncthreads();
    int nz = 0;
    for (int i = threadIdx.x; i < 2048; i += blockDim.x)
        nz |= (w[2 * i + 1] != 0);
    if (nz) atomicOr(&s_nonzero, 1);
    __syncthreads();
    if (threadIdx.x == 0) g_is64 = s_nonzero ? 0 : 1;
}

// ---------------- 0b. convert W1 to fp16 + zero degree (fused) ----------------
__global__ void k_prep(const float* __restrict__ W1, int n) {
    int i = blockIdx.x * blockDim.x + threadIdx.x;
    if (i < F0 * F1 / 2) {
        float2 v = *(const float2*)&W1[2 * i];
        *(__half2*)&g_w1h[2 * i] = __floats2half2_rn(v.x, v.y);
    }
    if (i < n) g_deg[i] = 0;
}

// ---------------- 2. count in-degree (4 edges/thread) ----------------
__global__ void k_count(const void* __restrict__ ei, int E) {
    int e = (blockIdx.x * blockDim.x + threadIdx.x) * 4;
    if (e >= E) return;
    if (((E & 3) == 0) && (e + 3 < E)) {
        int d0, d1, d2, d3;
        if (g_is64) {
            const int4* p = (const int4*)((const long long*)ei + (size_t)E + e);
            int4 a = p[0], b = p[1];
            d0 = a.x; d1 = a.z; d2 = b.x; d3 = b.z;
        } else {
            int4 a = *(const int4*)((const int*)ei + (size_t)E + e);
            d0 = a.x; d1 = a.y; d2 = a.z; d3 = a.w;
        }
        atomicAdd(&g_deg[d0], 1);
        atomicAdd(&g_deg[d1], 1);
        atomicAdd(&g_deg[d2], 1);
        atomicAdd(&g_deg[d3], 1);
    } else {
        for (int q = e; q < E && q < e + 4; q++) {
            int d = g_is64 ? (int)((const long long*)ei)[(size_t)E + q]
                           : ((const int*)ei)[(size_t)E + q];
            atomicAdd(&g_deg[d], 1);
        }
    }
}

// ---------------- 3a. per-block exclusive scan of deg ----------------
__global__ void k_scan_blk(int n) {
    __shared__ int s_wsum[32];
    int tid = threadIdx.x, lane = tid & 31, wid = tid >> 5;
    int i = blockIdx.x * 1024 + tid;
    int deg = (i < n) ? g_deg[i] : 0;
    int x = deg;
    #pragma unroll
    for (int o = 1; o < 32; o <<= 1) {
        int t = __shfl_up_sync(0xffffffffu, x, o);
        if (lane >= o) x += t;
    }
    if (lane == 31) s_wsum[wid] = x;
    __syncthreads();
    if (wid == 0) {
        int w = s_wsum[lane];
        #pragma unroll
        for (int o = 1; o < 32; o <<= 1) {
            int t = __shfl_up_sync(0xffffffffu, w, o);
            if (lane >= o) w += t;
        }
        s_wsum[lane] = w;
    }
    __syncthreads();
    int base = (wid ? s_wsum[wid - 1] : 0);
    if (i < n) g_rowstart[i] = base + x - deg;
    if (tid == 1023) g_blksum[blockIdx.x] = base + x;
}

// ---------------- 3b. scan of block sums (single block) ----------------
__global__ void k_scan_top(int nblk) {
    __shared__ int s_wsum[4];
    int tid = threadIdx.x, lane = tid & 31, wid = tid >> 5;
    int v = (tid < nblk) ? g_blksum[tid] : 0;
    int x = v;
    #pragma unroll
    for (int o = 1; o < 32; o <<= 1) {
        int t = __shfl_up_sync(0xffffffffu, x, o);
        if (lane >= o) x += t;
    }
    if (lane == 31) s_wsum[wid] = x;
    __syncthreads();
    if (tid < 4) {
        int w = s_wsum[tid];
        #pragma unroll
        for (int o = 1; o < 4; o <<= 1) {
            int t = __shfl_up_sync(0xfu, w, o);
            if ((tid & 3) >= o) w += t;
        }
        s_wsum[tid] = w;
    }
    __syncthreads();
    int base = (wid ? s_wsum[wid - 1] : 0);
    if (tid < nblk) g_blkoff[tid] = base + x - v;
}

// ---------------- 3c. add offsets, derive cursor + dinv ----------------
__global__ void k_scan_add(int n, int E) {
    int i = blockIdx.x * blockDim.x + threadIdx.x;
    if (i < n) {
        int rs = g_rowstart[i] + g_blkoff[blockIdx.x >> 2];
        g_rowstart[i] = rs;
        g_cursor[i]   = rs;
        g_dinv[i]     = rsqrtf((float)(g_deg[i] + 1));
    }
    if (i == 0) g_rowstart[n] = E;
}

// ---------------- 4. fill CSR (4 edges/thread) ----------------
__global__ void k_fill(const void* __restrict__ ei, int E) {
    int e = (blockIdx.x * blockDim.x + threadIdx.x) * 4;
    if (e >= E) return;
    if (((E & 3) == 0) && (e + 3 < E)) {
        int s0, s1, s2, s3, d0, d1, d2, d3;
        if (g_is64) {
            const int4* ps = (const int4*)((const long long*)ei + e);
            int4 a = ps[0], b = ps[1];
            s0 = a.x; s1 = a.z; s2 = b.x; s3 = b.z;
            const int4* pd = (const int4*)((const long long*)ei + (size_t)E + e);
            int4 c = pd[0], d = pd[1];
            d0 = c.x; d1 = c.z; d2 = d.x; d3 = d.z;
        } else {
            int4 a = *(const int4*)((const int*)ei + e);
            s0 = a.x; s1 = a.y; s2 = a.z; s3 = a.w;
            int4 b = *(const int4*)((const int*)ei + (size_t)E + e);
            d0 = b.x; d1 = b.y; d2 = b.z; d3 = b.w;
        }
        g_csr_src[atomicAdd(&g_cursor[d0], 1)] = s0;
        g_csr_src[atomicAdd(&g_cursor[d1], 1)] = s1;
        g_csr_src[atomicAdd(&g_cursor[d2], 1)] = s2;
        g_csr_src[atomicAdd(&g_cursor[d3], 1)] = s3;
    } else {
        for (int q = e; q < E && q < e + 4; q++) {
            int s, d;
            if (g_is64) {
                s = (int)((const long long*)ei)[q];
                d = (int)((const long long*)ei)[(size_t)E + q];
            } else {
                s = ((const int*)ei)[q];
                d = ((const int*)ei)[(size_t)E + q];
            }
            g_csr_src[atomicAdd(&g_cursor[d], 1)] = s;
        }
    }
}

// ---------------- 5. GEMM1 (tensor cores, cp.async pipelined, BK=32) ----------
// BM=64, BN=256 (full N -> x read once), BK=32, 8 warps, double-buffered.
// Per stage: sB 16KB + sA 5KB (pad rows to 40 halves: conflict-free, no swizzle)
// + raw 9KB (stride 36 floats = 144B, 16B-aligned). 2 stages = 60KB -> occ 2.
#define G1_SB_HALFS (32 * 256)       // 8192
#define G1_SA_STRIDE 40
#define G1_SA_HALFS (64 * G1_SA_STRIDE)   // 2560
#define G1_RAW_STRIDE 36
#define G1_RAW_FLTS (64 * G1_RAW_STRIDE)  // 2304
#define G1_SMEM (2 * (G1_SB_HALFS * 2 + G1_SA_HALFS * 2 + G1_RAW_FLTS * 4))

__device__ __forceinline__ void g1_stage(const float* __restrict__ A, int M, int row0,
                                         int kt, __half* sB, float* raw, int tid) {
    int k0 = kt * 32;
    // B: 32 rows x 32 chunks (16B) = 1024, 4/thread
    #pragma unroll
    for (int i = 0; i < 4; i++) {
        int cid = tid + i * 256;
        int r = cid >> 5, ch = cid & 31;
        cp16(&sB[r * 256 + ((ch ^ (r & 7)) * 8)],
             &g_w1h[(size_t)(k0 + r) * F1 + ch * 8]);
    }
    // A raw: 64 rows x 8 float4 = 512, 2/thread
    #pragma unroll
    for (int i = 0; i < 2; i++) {
        int cid = tid + i * 256;
        int r = cid >> 3, c = cid & 7;
        cp16z(&raw[r * G1_RAW_STRIDE + c * 4],
              &A[(size_t)(row0 + r) * F0 + k0 + c * 4], (row0 + r) < M);
    }
    asm volatile("cp.async.commit_group;");
}

__device__ __forceinline__ void g1_convert(__half* sA, const float* raw, int tid) {
    // 64 rows x 4 chunks (8 halves) = 256, 1/thread
    int r = tid >> 2, ch = tid & 3;
    const float* rp = &raw[r * G1_RAW_STRIDE + ch * 8];
    __half2 h0 = __floats2half2_rn(rp[0], rp[1]);
    __half2 h1 = __floats2half2_rn(rp[2], rp[3]);
    __half2 h2 = __floats2half2_rn(rp[4], rp[5]);
    __half2 h3 = __floats2half2_rn(rp[6], rp[7]);
    uint4 pk;
    pk.x = *(unsigned*)&h0; pk.y = *(unsigned*)&h1;
    pk.z = *(unsigned*)&h2; pk.w = *(unsigned*)&h3;
    *(uint4*)&sA[r * G1_SA_STRIDE + ch * 8] = pk;
}

__global__ __launch_bounds__(256, 2) void k_gemm1_tc(
    const float* __restrict__ A, int M
) {
    extern __shared__ __align__(16) char dyn[];
    __half* sBb  = (__half*)dyn;                                       // 2 x 16KB
    __half* sAb  = (__half*)(dyn + 2 * G1_SB_HALFS * 2);               // 2 x 5KB
    float*  rawb = (float*)(dyn + 2 * G1_SB_HALFS * 2 + 2 * G1_SA_HALFS * 2);
    int tid = threadIdx.x;
    int lane = tid & 31, wid = tid >> 5;
    int warp_m = wid & 1;
    int warp_n = wid >> 1;
    int row0 = blockIdx.x * 64;

    float acc[2][8][4];
    #pragma unroll
    for (int mt = 0; mt < 2; mt++)
        #pragma unroll
        for (int nt = 0; nt < 8; nt++)
            #pragma unroll
            for (int q = 0; q < 4; q++) acc[mt][nt][q] = 0.f;

    g1_stage(A, M, row0, 0, sBb, rawb, tid);
    asm volatile("cp.async.wait_group 0;");
    __syncthreads();
    g1_convert(sAb, rawb, tid);

    for (int kt = 0; kt < 16; kt++) {
        int cur = kt & 1, nxt = cur ^ 1;
        if (kt < 15)
            g1_stage(A, M, row0, kt + 1, sBb + nxt * G1_SB_HALFS,
                     rawb + nxt * G1_RAW_FLTS, tid);
        __syncthreads();   // convert(cur) visible to all warps

        const __half* sA = sAb + cur * G1_SA_HALFS;
        const __half* sB = sBb + cur * G1_SB_HALFS;
        #pragma unroll
        for (int ks = 0; ks < 2; ks++) {
            int kb = ks * 16;
            int j = lane >> 3;
            int jr = lane & 7;
            uint32_t afr[2][4];
            #pragma unroll
            for (int mt = 0; mt < 2; mt++) {
                int r = warp_m * 32 + mt * 16 + jr + ((j & 1) ? 8 : 0);
                int kk = kb + ((j & 2) ? 8 : 0);
                uint32_t addr = smem_u32(&sA[r * G1_SA_STRIDE + (kk >> 3) * 8]);
                asm volatile("ldmatrix.sync.aligned.m8n8.x4.shared.b16 {%0,%1,%2,%3}, [%4];"
                    : "=r"(afr[mt][0]), "=r"(afr[mt][1]), "=r"(afr[mt][2]), "=r"(afr[mt][3])
                    : "r"(addr));
            }
            uint32_t bfr[8][2];
            #pragma unroll
            for (int nq = 0; nq < 4; nq++) {
                int r = kb + jr + ((j & 1) ? 8 : 0);
                int nn = warp_n * 64 + nq * 16 + ((j & 2) ? 8 : 0);
                int ch = (nn >> 3) ^ (r & 7);
                uint32_t addr = smem_u32(&sB[r * 256 + ch * 8]);
                asm volatile("ldmatrix.sync.aligned.m8n8.x4.trans.shared.b16 {%0,%1,%2,%3}, [%4];"
                    : "=r"(bfr[nq * 2][0]), "=r"(bfr[nq * 2][1]),
                      "=r"(bfr[nq * 2 + 1][0]), "=r"(bfr[nq * 2 + 1][1])
                    : "r"(addr));
            }
            #pragma unroll
            for (int mt = 0; mt < 2; mt++)
                #pragma unroll
                for (int nt = 0; nt < 8; nt++) {
                    asm volatile(
                        "mma.sync.aligned.m16n8k16.row.col.f32.f16.f16.f32 "
                        "{%0,%1,%2,%3}, {%4,%5,%6,%7}, {%8,%9}, {%0,%1,%2,%3};"
                        : "+f"(acc[mt][nt][0]), "+f"(acc[mt][nt][1]),
                          "+f"(acc[mt][nt][2]), "+f"(acc[mt][nt][3])
                        : "r"(afr[mt][0]), "r"(afr[mt][1]), "r"(afr[mt][2]), "r"(afr[mt][3]),
                          "r"(bfr[nt][0]), "r"(bfr[nt][1]));
                }
        }

        if (kt < 15) {
            asm volatile("cp.async.wait_group 0;");
            __syncthreads();
            g1_convert(sAb + nxt * G1_SA_HALFS, rawb + nxt * G1_RAW_FLTS, tid);
        }
    }

    // epilogue: scale by dinv[row], pack fp16, store
    int quad = lane >> 2, tig = lane & 3;
    #pragma unroll
    for (int mt = 0; mt < 2; mt++) {
        int r0 = row0 + warp_m * 32 + mt * 16 + quad;
        int r1 = r0 + 8;
        float dv0 = (r0 < M) ? g_dinv[r0] : 0.f;
        float dv1 = (r1 < M) ? g_dinv[r1] : 0.f;
        #pragma unroll
        for (int nt = 0; nt < 8; nt++) {
            int c = warp_n * 64 + nt * 8 + tig * 2;
            if (r0 < M) {
                __half2 h = __floats2half2_rn(acc[mt][nt][0] * dv0, acc[mt][nt][1] * dv0);
                *(__half2*)&g_h1[(size_t)r0 * F1 + c] = h;
            }
            if (r1 < M) {
                __half2 h = __floats2half2_rn(acc[mt][nt][2] * dv1, acc[mt][nt][3] * dv1);
                *(__half2*)&g_h1[(size_t)r1 * F1 + c] = h;
            }
        }
    }
}

// ---------------- 6. agg1: one warp per dst node, fp16 gather / fp32 accum ----
__device__ __forceinline__ void acc_row(float* acc, uint4 v) {
    const __half2* h = (const __half2*)&v;
    #pragma unroll
    for (int q = 0; q < 4; q++) {
        float2 f = __half22float2(h[q]);
        acc[2 * q]     += f.x;
        acc[2 * q + 1] += f.y;
    }
}

__global__ void k_agg1(const float* __restrict__ b1, int n) {
    int w = (blockIdx.x * blockDim.x + threadIdx.x) >> 5;
    if (w >= n) return;
    int lane = threadIdx.x & 31;
    int beg = g_rowstart[w], end = g_rowstart[w + 1];
    const size_t laneoff = (size_t)lane * 8;
    float acc[8];
    {
        uint4 v = *(const uint4*)&g_h1[(size_t)w * F1 + laneoff];
        const __half2* h = (const __half2*)&v;
        #pragma unroll
        for (int q = 0; q < 4; q++) {
            float2 f = __half22float2(h[q]);
            acc[2 * q] = f.x;
            acc[2 * q + 1] = f.y;
        }
    }
    int p = beg;
    for (; p + 1 < end; p += 2) {
        int s0 = g_csr_src[p];
        int s1 = g_csr_src[p + 1];
        uint4 v0 = *(const uint4*)&g_h1[(size_t)s0 * F1 + laneoff];
        uint4 v1 = *(const uint4*)&g_h1[(size_t)s1 * F1 + laneoff];
        acc_row(acc, v0);
        acc_row(acc, v1);
    }
    if (p < end) {
        int s0 = g_csr_src[p];
        uint4 v0 = *(const uint4*)&g_h1[(size_t)s0 * F1 + laneoff];
        acc_row(acc, v0);
    }
    float dv = g_dinv[w];
    float4 bb0 = *(const float4*)&b1[laneoff];
    float4 bb1 = *(const float4*)&b1[laneoff + 4];
    __half2 o[4];
    o[0] = __floats2half2_rn(fmaxf(acc[0] * dv + bb0.x, 0.f), fmaxf(acc[1] * dv + bb0.y, 0.f));
    o[1] = __floats2half2_rn(fmaxf(acc[2] * dv + bb0.z, 0.f), fmaxf(acc[3] * dv + bb0.w, 0.f));
    o[2] = __floats2half2_rn(fmaxf(acc[4] * dv + bb1.x, 0.f), fmaxf(acc[5] * dv + bb1.y, 0.f));
    o[3] = __floats2half2_rn(fmaxf(acc[6] * dv + bb1.z, 0.f), fmaxf(acc[7] * dv + bb1.w, 0.f));
    uint4 pk;
    pk.x = *(unsigned*)&o[0]; pk.y = *(unsigned*)&o[1];
    pk.z = *(unsigned*)&o[2]; pk.w = *(unsigned*)&o[3];
    *(uint4*)&g_a1[(size_t)w * F1 + laneoff] = pk;
}

// ---------------- 7. GEMM2 (tensor cores): g_h2 = fp16((a1 @ W2) * dinv[row]) --
__global__ __launch_bounds__(256, 2) void k_gemm2_tc(const float* __restrict__ W2, int M) {
    __shared__ __align__(16) __half sA[128 * 64];
    __shared__ __align__(16) __half sW[64 * 40];
    int tid = threadIdx.x;
    int lane = tid & 31, wid = tid >> 5;
    int row0 = blockIdx.x * 128;

    float acc[5][4];
    #pragma unroll
    for (int nt = 0; nt < 5; nt++)
        #pragma unroll
        for (int q = 0; q < 4; q++) acc[nt][q] = 0.f;

    for (int k0 = 0; k0 < F1; k0 += 64) {
        #pragma unroll
        for (int i = 0; i < 4; i++) {
            int cid = tid + i * 256;
            int r = cid >> 3, ch = cid & 7;
            int gr = row0 + r;
            uint4 pk = make_uint4(0, 0, 0, 0);
            if (gr < M) pk = *(const uint4*)&g_a1[(size_t)gr * F1 + k0 + ch * 8];
            int sch = ch ^ (r & 7);
            *(uint4*)&sA[r * 64 + sch * 8] = pk;
        }
        #pragma unroll
        for (int i = 0; i < 10; i++) {
            int idx = tid + i * 256;
            int r = idx / 40, c = idx % 40;
            sW[r * 40 + c] = __float2half(W2[(size_t)(k0 + r) * F2 + c]);
        }
        __syncthreads();

        #pragma unroll
        for (int ks = 0; ks < 4; ks++) {
            int kb = ks * 16;
            int j = lane >> 3;
            int jr = lane & 7;
            uint32_t afr[4];
            {
                int r = wid * 16 + jr + ((j & 1) ? 8 : 0);
                int kk = kb + ((j & 2) ? 8 : 0);
                int ch = (kk >> 3) ^ (r & 7);
                uint32_t addr = smem_u32(&sA[r * 64 + ch * 8]);
                asm volatile("ldmatrix.sync.aligned.m8n8.x4.shared.b16 {%0,%1,%2,%3}, [%4];"
                    : "=r"(afr[0]), "=r"(afr[1]), "=r"(afr[2]), "=r"(afr[3])
                    : "r"(addr));
            }
            uint32_t bfr[5][2];
            #pragma unroll
            for (int nq = 0; nq < 2; nq++) {
                int r = kb + jr + ((j & 1) ? 8 : 0);
                int nn = nq * 16 + ((j & 2) ? 8 : 0);
                uint32_t addr = smem_u32(&sW[r * 40 + nn]);
                asm volatile("ldmatrix.sync.aligned.m8n8.x4.trans.shared.b16 {%0,%1,%2,%3}, [%4];"
                    : "=r"(bfr[nq * 2][0]), "=r"(bfr[nq * 2][1]),
                      "=r"(bfr[nq * 2 + 1][0]), "=r"(bfr[nq * 2 + 1][1])
                    : "r"(addr));
            }
            {
                int j2 = (lane >> 3) & 1;
                int r = kb + jr + (j2 ? 8 : 0);
                uint32_t addr = smem_u32(&sW[r * 40 + 32]);
                asm volatile("ldmatrix.sync.aligned.m8n8.x2.trans.shared.b16 {%0,%1}, [%2];"
                    : "=r"(bfr[4][0]), "=r"(bfr[4][1])
                    : "r"(addr));
            }
            #pragma unroll
            for (int nt = 0; nt < 5; nt++) {
                asm volatile(
                    "mma.sync.aligned.m16n8k16.row.col.f32.f16.f16.f32 "
                    "{%0,%1,%2,%3}, {%4,%5,%6,%7}, {%8,%9}, {%0,%1,%2,%3};"
                    : "+f"(acc[nt][0]), "+f"(acc[nt][1]), "+f"(acc[nt][2]), "+f"(acc[nt][3])
                    : "r"(afr[0]), "r"(afr[1]), "r"(afr[2]), "r"(afr[3]),
                      "r"(bfr[nt][0]), "r"(bfr[nt][1]));
            }
        }
        __syncthreads();
    }

    int quad = lane >> 2, tig = lane & 3;
    int r0 = row0 + wid * 16 + quad;
    int r1 = r0 + 8;
    float dv0 = (r0 < M) ? g_dinv[r0] : 0.f;
    float dv1 = (r1 < M) ? g_dinv[r1] : 0.f;
    #pragma unroll
    for (int nt = 0; nt < 5; nt++) {
        int c = nt * 8 + tig * 2;
        if (r0 < M) {
            __half2 h = __floats2half2_rn(acc[nt][0] * dv0, acc[nt][1] * dv0);
            *(__half2*)&g_h2[(size_t)r0 * F2 + c] = h;
        }
        if (r1 < M) {
            __half2 h = __floats2half2_rn(acc[nt][2] * dv1, acc[nt][3] * dv1);
            *(__half2*)&g_h2[(size_t)r1 * F2 + c] = h;
        }
    }
}

// ---------------- 8. agg2 + bias + log_softmax: one warp per node ----------------
__global__ void k_agg2(const float* __restrict__ b2, float* __restrict__ out, int n) {
    int w = (blockIdx.x * blockDim.x + threadIdx.x) >> 5;
    if (w >= n) return;
    int lane = threadIdx.x & 31;
    int beg = g_rowstart[w], end = g_rowstart[w + 1];
    const __half* selfr = &g_h2[(size_t)w * F2];
    float a0 = __half2float(selfr[lane]);
    float a1 = (lane < 8) ? __half2float(selfr[32 + lane]) : 0.f;
    for (int p = beg; p < end; p++) {
        int s = g_csr_src[p];
        const __half* r = &g_h2[(size_t)s * F2];
        a0 += __half2float(r[lane]);
        if (lane < 8) a1 += __half2float(r[32 + lane]);
    }
    float dv = g_dinv[w];
    const float NEGINF = __int_as_float(0xff800000);
    float v0 = a0 * dv + b2[lane];
    float v1 = (lane < 8) ? (a1 * dv + b2[32 + lane]) : NEGINF;
    float m = fmaxf(v0, v1);
    #pragma unroll
    for (int o = 16; o; o >>= 1) m = fmaxf(m, __shfl_xor_sync(0xffffffffu, m, o));
    float s1 = __expf(v0 - m) + ((lane < 8) ? __expf(v1 - m) : 0.f);
    #pragma unroll
    for (int o = 16; o; o >>= 1) s1 += __shfl_xor_sync(0xffffffffu, s1, o);
    float ls = m + __logf(s1);
    out[(size_t)w * F2 + lane] = v0 - ls;
    if (lane < 8) out[(size_t)w * F2 + 32 + lane] = v1 - ls;
}

// ---------------- launch ----------------
extern "C" void kernel_launch(void* const* d_in, const int* in_sizes, int n_in,
                              void* d_out, int out_size) {
    const float* x  = (const float*)d_in[0];
    const void*  ei = (const void*)d_in[1];
    const float* W1 = (const float*)d_in[2];
    const float* b1 = (const float*)d_in[3];
    const float* W2 = (const float*)d_in[4];
    const float* b2 = (const float*)d_in[5];
    float* out = (float*)d_out;

    int n = in_sizes[0] / F0;     // 100000
    int E = in_sizes[1] / 2;      // 3200000
    int nblk = (n + 1023) >> 10;
    int prep_items = (F0 * F1 / 2 > n) ? F0 * F1 / 2 : n;

    cudaFuncSetAttribute(k_gemm1_tc, cudaFuncAttributeMaxDynamicSharedMemorySize, G1_SMEM);

    k_detect<<<1, 256>>>((const int*)ei);
    k_prep<<<(prep_items + 255) / 256, 256>>>(W1, n);
    k_count<<<(E / 4 + 255) / 256, 256>>>(ei, E);
    k_scan_blk<<<nblk, 1024>>>(n);
    k_scan_top<<<1, 128>>>(nblk);
    k_scan_add<<<(n + 255) / 256, 256>>>(n, E);
    k_fill<<<(E / 4 + 255) / 256, 256>>>(ei, E);

    k_gemm1_tc<<<(n + 63) / 64, 256, G1_SMEM>>>(x, n);

    k_agg1<<<(n * 32 + 255) / 256, 256>>>(b1, n);

    k_gemm2_tc<<<(n + 127) / 128, 256>>>(W2, n);

    k_agg2<<<(n * 32 + 255) / 256, 256>>>(b2, out, n);
}